// round 6
// baseline (speedup 1.0000x reference)
#include <cuda_runtime.h>
#include <cstdint>

// ---------------------------------------------------------------------------
// HebbianConv2d (sm_103 baseline ISA):
//   valid 3x3 conv (16,256,56,56)->(16,384,54,54) as implicit GEMM on the
//   FFMA f32x2 pipe. All operand duplication/swizzling is precomputed:
//   W is stored pre-duplicated ({a,a} pairs) in the exact stage-major smem
//   image, so the hot loop is pure cp.async + 6 conflict-free LDS.128 +
//   32 FFMA2 per k-slice. 128x128 tile, KS=32, 2-slot pipeline, 256 thr,
//   2 CTAs/SM. Then per-pixel WTA + Gaussian LFB gating.
// ---------------------------------------------------------------------------

#define B_SZ   16
#define CIN_   256
#define COUT_  384
#define HIN_   56
#define HO_    54
#define KDIM   2304                  // 256*9
#define IMG_N  3072                  // padded local-n per image
#define NPAD   (B_SZ * IMG_N)
#define IMG_SZ (CIN_ * HIN_ * HIN_)  // 802816
#define XELEMS ((size_t)B_SZ * IMG_SZ)
#define XP     (XELEMS + 4096)

#define KS      32
#define NSTAGE  (KDIM / KS)                     // 72
#define ASTG_F  (KS * 128 * 2)                  // 8192 floats per A stage block
#define WT2_F   (3 * NSTAGE * ASTG_F)           // 1,769,472

typedef unsigned long long ull;

__device__ float g_xs[3 * XP];          // kw-shifted copies of x
__device__ float g_wt2[WT2_F];          // A pre-dup'd, stage-major smem image
__device__ float g_y[(size_t)NPAD * COUT_];
__device__ float g_pad;

__device__ __forceinline__ void ffma2(ull &c, ull a, ull b) {
    asm("fma.rn.f32x2 %0, %1, %2, %0;" : "+l"(c) : "l"(a), "l"(b));
}
__device__ __forceinline__ uint32_t smem_u32(const void* p) {
    uint32_t a;
    asm("{ .reg .u64 t; cvta.to.shared.u64 t, %1; cvt.u32.u64 %0, t; }"
        : "=r"(a) : "l"(p));
    return a;
}
__device__ __forceinline__ void cp16(uint32_t dst, const float* src) {
    asm volatile("cp.async.cg.shared.global [%0], [%1], 16;"
                 :: "r"(dst), "l"(src) : "memory");
}
#define CP_COMMIT() asm volatile("cp.async.commit_group;" ::: "memory")
#define CP_WAIT1()  asm volatile("cp.async.wait_group 1;" ::: "memory")

// ---------------------------------------------------------------------------
__global__ void copy_x3_kernel(const float* __restrict__ x) {
    size_t i = (size_t)blockIdx.x * 256 + threadIdx.x;
    size_t n4 = XELEMS / 4;
    if (i < n4) {
        float4 a = ((const float4*)x)[i];
        float4 b = (i + 1 < n4) ? ((const float4*)x)[i + 1] : a;
        ((float4*)g_xs)[i]            = a;
        ((float4*)(g_xs + XP))[i]     = make_float4(a.y, a.z, a.w, b.x);
        ((float4*)(g_xs + 2 * XP))[i] = make_float4(a.z, a.w, b.x, b.y);
    }
}

// Build g_wt2: for each m-tile and k-stage, a 32KB block that is byte-for-byte
// the smem A slot: row r (k within stage) has 64 chunks of 16B; chunk
// (q*16 + gm) holds floats {a,a,a',a'} for m = gm*8 + q*2 (+1), duplicated.
__global__ void dupw_kernel(const float* __restrict__ w) {
    int o = blockIdx.x * 256 + threadIdx.x;
    if (o < WT2_F) {
        int mtile = o / (NSTAGE * ASTG_F);
        int r1 = o - mtile * (NSTAGE * ASTG_F);
        int s  = r1 / ASTG_F;
        int r2 = r1 - s * ASTG_F;
        int r  = r2 >> 8;                 // k-row in stage (256 floats/row)
        int r3 = r2 & 255;
        int c  = r3 >> 2;                 // chunk 0..63
        int f  = r3 & 3;
        int q  = c >> 4;
        int gm = c & 15;
        int mloc = gm * 8 + q * 2 + (f >> 1);
        int k = s * KS + r;
        g_wt2[o] = w[(size_t)(mtile * 128 + mloc) * KDIM + k];
    }
}

__global__ void pad_kernel() { if (threadIdx.x == 0) g_pad = 1.0f; }

// ---------------------------------------------------------------------------
// Conv GEMM: tile M=128 x N=128, KS=32, 2 slots x 48KB, 256 threads, 2 CTAs/SM.
// Slot: A-dup 32KB (rows of 1024B) | B 16KB (rows of 512B).
// ---------------------------------------------------------------------------
#define SLOT_B    (48 * 1024)
#define SMEM_CONV (2 * SLOT_B)                  // 96KB

__global__ __launch_bounds__(256, 2)
void conv_gemm_kernel()
{
    extern __shared__ char smem[];
    const uint32_t sb = smem_u32(smem);

    const int tid  = threadIdx.x;
    const int lane = tid & 31;
    const int wid  = tid >> 5;

    // thread microtile: 8m x 8n
    const int gm0 = (lane >> 2) + (wid & 1) * 8;       // m-group 0..15
    const int tm  = gm0 * 8;
    const int tn  = (lane & 3) * 8 + (wid >> 1) * 32;

    const int mtile = blockIdx.x;
    const int m0    = mtile * 128;
    const int bimg  = blockIdx.y / 24;
    const int nl0   = (blockIdx.y - bimg * 24) * 128;
    const int imgb  = bimg * IMG_SZ;

    const float* Awt = g_wt2 + (size_t)(mtile * NSTAGE) * ASTG_F;

    ull acc[8][4];
#pragma unroll
    for (int i = 0; i < 8; i++)
#pragma unroll
        for (int j = 0; j < 4; j++) acc[i][j] = 0ull;

    auto issue_stage = [&](int s, int slot) {
        const uint32_t sa = sb + slot * SLOT_B;
        const float* ab = Awt + (size_t)s * ASTG_F;
        // A: 2048 chunks, 8 per thread, flat copy
#pragma unroll
        for (int j = 0; j < 8; j++) {
            int cid = j * 256 + tid;
            cp16(sa + cid * 16, ab + cid * 4);
        }
        // B: 1024 chunks; row = k within stage, 32 chunks/row
        const int k0 = s * KS;
#pragma unroll
        for (int j = 0; j < 4; j++) {
            int row = j * 8 + wid;           // (j*256+tid)>>5
            int cin = lane;                   // chunk in row (lane 0..31)
            int k  = k0 + row;
            int ci = k / 9;
            int r  = k - ci * 9;
            int kh = r / 3;
            int kw = r - kh * 3;
            const float* src = g_xs + (size_t)kw * XP + imgb
                             + ci * (HIN_ * HIN_) + kh * HIN_ + nl0 + cin * 4;
            cp16(sa + 32768 + row * 512 + cin * 16, src);
        }
        CP_COMMIT();
    };

    auto compute_stage = [&](int slot) {
        const char* base = smem + slot * SLOT_B;
        const char* Ab = base + gm0 * 16;
        const char* Bb = base + 32768 + tn * 4;
#pragma unroll
        for (int kk = 0; kk < KS; kk++) {
            ull ad[8];
#pragma unroll
            for (int q = 0; q < 4; q++) {
                ulonglong2 v = *(const ulonglong2*)(Ab + kk * 1024 + q * 256);
                ad[2 * q]     = v.x;
                ad[2 * q + 1] = v.y;
            }
            ulonglong2 b0 = *(const ulonglong2*)(Bb + kk * 512);
            ulonglong2 b1 = *(const ulonglong2*)(Bb + kk * 512 + 16);
            ull bb[4] = { b0.x, b0.y, b1.x, b1.y };
#pragma unroll
            for (int mi = 0; mi < 8; mi++)
#pragma unroll
                for (int nj = 0; nj < 4; nj++)
                    ffma2(acc[mi][nj], ad[mi], bb[nj]);
        }
    };

    issue_stage(0, 0);
    issue_stage(1, 1);
    for (int s = 0; s < NSTAGE; s++) {
        CP_WAIT1();                  // stage s landed (s+1 may be in flight)
        __syncthreads();
        compute_stage(s & 1);
        __syncthreads();
        if (s + 2 < NSTAGE) issue_stage(s + 2, s & 1);
        else CP_COMMIT();            // keep group accounting consistent
    }

    // ---- store: g_y[padded n][m] ----
    const int n0g = bimg * IMG_N + nl0;
    union { ull u; float f[2]; } cv;
#pragma unroll
    for (int nj = 0; nj < 4; nj++) {
#pragma unroll
        for (int d = 0; d < 2; d++) {
            int n = n0g + tn + nj * 2 + d;
            float v[8];
#pragma unroll
            for (int mi = 0; mi < 8; mi++) { cv.u = acc[mi][nj]; v[mi] = cv.f[d]; }
            float* dst = g_y + (size_t)n * COUT_ + m0 + tm;
            *(float4*)(dst + 0) = make_float4(v[0], v[1], v[2], v[3]);
            *(float4*)(dst + 4) = make_float4(v[4], v[5], v[6], v[7]);
        }
    }
}

// ---------------------------------------------------------------------------
// WTA + Gaussian lateral feedback gating (27 pixels per block)
// ---------------------------------------------------------------------------
#define SYP 388

__global__ __launch_bounds__(256) void wta_lfb_kernel(float* __restrict__ out) {
    __shared__ float sy[27 * SYP];
    __shared__ int   wcnt[27];
    __shared__ int   wlist[27][4];

    const int tid = threadIdx.x;
    const int b   = blockIdx.z;
    const int h   = blockIdx.y;
    const int w0  = blockIdx.x * 27;

    const size_t base = ((size_t)b * IMG_N + h * HIN_ + w0) * COUT_;

    for (int i4 = tid; i4 < 27 * 96; i4 += 256) {
        float4 v = *(const float4*)(g_y + base + (size_t)i4 * 4);
        int j  = i4 / 96;
        int c4 = i4 - j * 96;
        *(float4*)&sy[j * SYP + c4 * 4] = v;
    }
    if (tid < 27) wcnt[tid] = 0;
    __syncthreads();

    const int wid  = tid >> 5;
    const int lane = tid & 31;
    for (int j = wid; j < 27; j += 8) {
        const float* p = &sy[j * SYP];
        float mx = -3.4e38f;
#pragma unroll
        for (int q = 0; q < 12; q++) mx = fmaxf(mx, p[lane + q * 32]);
#pragma unroll
        for (int o = 16; o; o >>= 1) mx = fmaxf(mx, __shfl_xor_sync(0xffffffffu, mx, o));
#pragma unroll
        for (int q = 0; q < 12; q++) {
            int c = lane + q * 32;
            if (p[c] == mx) {
                int pos = atomicAdd(&wcnt[j], 1);
                if (pos < 4) wlist[j][pos] = c;
            }
        }
    }
    __syncthreads();

    const float inv2s2 = 1.0f / (2.0f * 191.0f * 191.0f);
    for (int i = tid; i < COUT_ * 27; i += 256) {
        int c = i / 27;
        int j = i - c * 27;
        float yv = sy[j * SYP + c];
        int nw = wcnt[j]; if (nw > 4) nw = 4;
        float lfb = 0.0f;
        for (int t = 0; t < nw; t++) {
            int d = wlist[j][t] - c;
            if (d >= -191 && d <= 192)
                lfb += __expf(-(float)(d * d) * inv2s2);
        }
        lfb = fminf(lfb, 1.0f);
        out[(((size_t)b * COUT_ + c) * HO_ + h) * HO_ + w0 + j] = lfb * yv;
    }
}

// ---------------------------------------------------------------------------
extern "C" void kernel_launch(void* const* d_in, const int* in_sizes, int n_in,
                              void* d_out, int out_size) {
    const float* x = (const float*)d_in[0];   // (16,256,56,56)
    const float* w = (const float*)d_in[1];   // (384,256,3,3)
    float* out = (float*)d_out;               // (16,384,54,54)

    cudaFuncSetAttribute(conv_gemm_kernel,
                         cudaFuncAttributeMaxDynamicSharedMemorySize, SMEM_CONV);

    copy_x3_kernel<<<(unsigned)((XELEMS / 4 + 255) / 256), 256>>>(x);
    dupw_kernel<<<(WT2_F + 255) / 256, 256>>>(w);
    pad_kernel<<<1, 32>>>();                  // keeps conv at replay idx 3 (ncu -s 5)

    dim3 g1(3, B_SZ * 24);                    // m fastest -> B reuse in L2
    conv_gemm_kernel<<<g1, 256, SMEM_CONV>>>();

    dim3 g2(2, HO_, B_SZ);
    wta_lfb_kernel<<<g2, 256>>>(out);
}

// round 7
// speedup vs baseline: 1.1702x; 1.1702x over previous
#include <cuda_runtime.h>
#include <cstdint>

// ---------------------------------------------------------------------------
// HebbianConv2d (sm_103 baseline ISA):
//   valid 3x3 conv (16,256,56,56)->(16,384,54,54) as implicit GEMM on the
//   FFMA f32x2 pipe (R5 structure: cp.async 3-slot pipeline, A as [k][m]
//   m-contiguous f32x2 pairs, B dup'd in registers). WTA epilogue uses a
//   precomputed Gaussian LFB table (no MUFU, no divisions).
// ---------------------------------------------------------------------------

#define B_SZ   16
#define CIN_   256
#define COUT_  384
#define HIN_   56
#define HO_    54
#define KDIM   2304                  // 256*9
#define IMG_N  3072                  // padded local-n per image
#define NPAD   (B_SZ * IMG_N)        // 49152
#define IMG_SZ (CIN_ * HIN_ * HIN_)  // 802816
#define XELEMS ((size_t)B_SZ * IMG_SZ)
#define XP     (XELEMS + 4096)

typedef unsigned long long ull;

__device__ float g_xs[3 * XP];                  // kw-shifted copies of x
__device__ float g_wt[KDIM * COUT_];            // W transposed: [k][m]
__device__ float g_y[(size_t)NPAD * COUT_];     // pixel-major [padded n][m]
__device__ float g_lfbtab[768];                 // Gaussian LFB vs (d+383)

__device__ __forceinline__ void ffma2(ull &c, ull a, ull b) {
    asm("fma.rn.f32x2 %0, %1, %2, %0;" : "+l"(c) : "l"(a), "l"(b));
}
__device__ __forceinline__ ull dup2(float a) {
    ull r;
    asm("mov.b64 %0, {%1, %1};" : "=l"(r) : "f"(a));
    return r;
}
__device__ __forceinline__ uint32_t smem_u32(const void* p) {
    uint32_t a;
    asm("{ .reg .u64 t; cvta.to.shared.u64 t, %1; cvt.u32.u64 %0, t; }"
        : "=r"(a) : "l"(p));
    return a;
}
__device__ __forceinline__ void cp16(uint32_t dst, const float* src) {
    asm volatile("cp.async.cg.shared.global [%0], [%1], 16;"
                 :: "r"(dst), "l"(src) : "memory");
}
#define CP_COMMIT() asm volatile("cp.async.commit_group;" ::: "memory")
#define CP_WAIT1()  asm volatile("cp.async.wait_group 1;" ::: "memory")

// ---------------------------------------------------------------------------
__global__ void copy_x3_kernel(const float* __restrict__ x) {
    size_t i = (size_t)blockIdx.x * 256 + threadIdx.x;
    size_t n4 = XELEMS / 4;
    if (i < n4) {
        float4 a = ((const float4*)x)[i];
        float4 b = (i + 1 < n4) ? ((const float4*)x)[i + 1] : a;
        ((float4*)g_xs)[i]            = a;
        ((float4*)(g_xs + XP))[i]     = make_float4(a.y, a.z, a.w, b.x);
        ((float4*)(g_xs + 2 * XP))[i] = make_float4(a.z, a.w, b.x, b.y);
    }
}

__global__ void transpose_w_kernel(const float* __restrict__ w) {
    int i = blockIdx.x * 256 + threadIdx.x;     // i = m*KDIM + k
    if (i < COUT_ * KDIM) {
        int m = i / KDIM;
        int k = i - m * KDIM;
        g_wt[k * COUT_ + m] = w[i];
    }
}

__global__ void lfbtab_kernel() {               // tiny; also ncu alignment slot
    int i = blockIdx.x * 256 + threadIdx.x;
    if (i < 768) {
        int d = i - 383;
        float v = 0.0f;
        if (d >= -191 && d <= 192)
            v = expf(-(float)(d * d) / (2.0f * 191.0f * 191.0f));
        g_lfbtab[i] = v;
    }
}

// ---------------------------------------------------------------------------
// Conv GEMM: tile M=128 x N=128, KS=32, 256 threads, 2 CTAs/SM.
// SMEM: 3 slots x (A 16KB + B 16KB) = 96KB. cp.async pipeline depth 3.
// (structure identical to R5 best; kk unroll 16 for I$)
// ---------------------------------------------------------------------------
#define KS        32
#define SLOT_B    (2 * KS * 128 * 4)            // 32KB per slot
#define SMEM_CONV (3 * SLOT_B)                  // 96KB
#define NSTAGE    (KDIM / KS)                   // 72

__global__ __launch_bounds__(256, 2)
void conv_gemm_kernel()
{
    extern __shared__ char smem[];
    const uint32_t sb = smem_u32(smem);

    const int tid  = threadIdx.x;
    const int lane = tid & 31;
    const int wid  = tid >> 5;                  // 0..7

    // warp grid: 2 m-warps x 4 n-warps; lane grid: 8 m-groups x 4 n-groups
    const int tm = (lane >> 2) * 8 + (wid & 1) * 64;   // 8 m per thread
    const int tn = (lane & 3) * 8 + (wid >> 1) * 32;   // 8 n per thread

    const int m0   = blockIdx.x * 128;
    const int bimg = blockIdx.y / 24;
    const int nl0  = (blockIdx.y - bimg * 24) * 128;
    const int imgb = bimg * IMG_SZ;

    const float* Abase = g_wt + m0 + lane * 4;          // + k*384
    const int    bcol  = nl0 + lane * 4;

    ull acc[4][8];
#pragma unroll
    for (int i = 0; i < 4; i++)
#pragma unroll
        for (int j = 0; j < 8; j++) acc[i][j] = 0ull;

    auto issue_stage = [&](int s, int slot) {
        const int k0 = s * KS;
        const uint32_t sa = sb + slot * SLOT_B;
#pragma unroll
        for (int j = 0; j < 4; j++) {
            int row = j * 8 + wid;
            cp16(sa + row * 512 + lane * 16, Abase + (size_t)(k0 + row) * COUT_);
        }
#pragma unroll
        for (int j = 0; j < 4; j++) {
            int row = j * 8 + wid;
            int k  = k0 + row;
            int ci = k / 9;
            int r  = k - ci * 9;
            int kh = r / 3;
            int kw = r - kh * 3;
            const float* src = g_xs + (size_t)kw * XP + imgb
                             + ci * (HIN_ * HIN_) + kh * HIN_ + bcol;
            cp16(sa + 16384 + row * 512 + lane * 16, src);
        }
        CP_COMMIT();
    };

    auto compute_stage = [&](int slot) {
        const char* base = smem + slot * SLOT_B;
        const float* Ab = (const float*)base + tm;
        const float* Bb = (const float*)(base + 16384) + tn;
#pragma unroll 16
        for (int kk = 0; kk < KS; kk++) {
            ulonglong2 a01 = *(const ulonglong2*)(Ab + kk * 128);
            ulonglong2 a23 = *(const ulonglong2*)(Ab + kk * 128 + 4);
            ull a[4] = { a01.x, a01.y, a23.x, a23.y };

            float4 b0 = *(const float4*)(Bb + kk * 128);
            float4 b1 = *(const float4*)(Bb + kk * 128 + 4);
            ull bd[8] = { dup2(b0.x), dup2(b0.y), dup2(b0.z), dup2(b0.w),
                          dup2(b1.x), dup2(b1.y), dup2(b1.z), dup2(b1.w) };

#pragma unroll
            for (int mi = 0; mi < 4; mi++)
#pragma unroll
                for (int nj = 0; nj < 8; nj++)
                    ffma2(acc[mi][nj], a[mi], bd[nj]);
        }
    };

    issue_stage(0, 0);
    issue_stage(1, 1);
    for (int s = 0; s < NSTAGE; s++) {
        CP_WAIT1();                 // stage s landed
        __syncthreads();            // all threads done with compute(s-1)
        if (s + 2 < NSTAGE) issue_stage(s + 2, (s + 2) % 3);
        else CP_COMMIT();           // keep group accounting consistent
        compute_stage(s % 3);
    }

    // ---- store: g_y[padded n][m] (8 consecutive m per thread) ----
    const int n0g = bimg * IMG_N + nl0;
    union { ull u; float f[2]; } c0, c1;
#pragma unroll
    for (int nj = 0; nj < 8; nj++) {
        int n = n0g + tn + nj;
        float* dst = g_y + (size_t)n * COUT_ + m0 + tm;
        c0.u = acc[0][nj]; c1.u = acc[1][nj];
        *(float4*)(dst + 0) = make_float4(c0.f[0], c0.f[1], c1.f[0], c1.f[1]);
        c0.u = acc[2][nj]; c1.u = acc[3][nj];
        *(float4*)(dst + 4) = make_float4(c0.f[0], c0.f[1], c1.f[0], c1.f[1]);
    }
}

// ---------------------------------------------------------------------------
// WTA + Gaussian LFB gating (27 pixels/block), table-based (no exp, no div)
// ---------------------------------------------------------------------------
#define SYP 388

__global__ __launch_bounds__(256) void wta_lfb_kernel(float* __restrict__ out) {
    __shared__ float sy[27 * SYP];
    __shared__ float stab[768];
    __shared__ int   wcnt[27];
    __shared__ int   wlist[27][4];

    const int tid = threadIdx.x;
    const int b   = blockIdx.z;
    const int h   = blockIdx.y;
    const int w0  = blockIdx.x * 27;

    const size_t base = ((size_t)b * IMG_N + h * HIN_ + w0) * COUT_;

    for (int i4 = tid; i4 < 27 * 96; i4 += 256) {
        float4 v = *(const float4*)(g_y + base + (size_t)i4 * 4);
        int j  = i4 / 96;
        int c4 = i4 - j * 96;
        *(float4*)&sy[j * SYP + c4 * 4] = v;
    }
    if (tid < 192) {
        float4 t = *(const float4*)(g_lfbtab + tid * 4);
        *(float4*)&stab[tid * 4] = t;
    }
    if (tid < 27) wcnt[tid] = 0;
    __syncthreads();

    const int wd   = tid >> 5;
    const int lane = tid & 31;
    for (int j = wd; j < 27; j += 8) {
        const float* p = &sy[j * SYP];
        float mx = -3.4e38f;
#pragma unroll
        for (int q = 0; q < 12; q++) mx = fmaxf(mx, p[lane + q * 32]);
#pragma unroll
        for (int o = 16; o; o >>= 1) mx = fmaxf(mx, __shfl_xor_sync(0xffffffffu, mx, o));
#pragma unroll
        for (int q = 0; q < 12; q++) {
            int c = lane + q * 32;
            if (p[c] == mx) {
                int pos = atomicAdd(&wcnt[j], 1);
                if (pos < 4) wlist[j][pos] = c;
            }
        }
    }
    __syncthreads();

    // gating: i = c*27 + j, incremental stepping (no division in loop)
    int c = tid / 27;
    int j = tid - c * 27;
    const size_t obase = (((size_t)b * COUT_) * HO_ + h) * HO_ + w0;
    while (c < COUT_) {
        float yv = sy[j * SYP + c];
        int nw = wcnt[j];
        float lfb = stab[wlist[j][0] - c + 383];
        if (nw > 1) {
            if (nw > 4) nw = 4;
            for (int t = 1; t < nw; t++)
                lfb += stab[wlist[j][t] - c + 383];
            lfb = fminf(lfb, 1.0f);
        }
        out[obase + (size_t)c * (HO_ * HO_) + j] = lfb * yv;
        // advance by 256: c += 9, j += 13 (256 = 9*27 + 13)
        c += 9; j += 13;
        if (j >= 27) { j -= 27; c += 1; }
    }
}

// ---------------------------------------------------------------------------
extern "C" void kernel_launch(void* const* d_in, const int* in_sizes, int n_in,
                              void* d_out, int out_size) {
    const float* x = (const float*)d_in[0];   // (16,256,56,56)
    const float* w = (const float*)d_in[1];   // (384,256,3,3)
    float* out = (float*)d_out;               // (16,384,54,54)

    cudaFuncSetAttribute(conv_gemm_kernel,
                         cudaFuncAttributeMaxDynamicSharedMemorySize, SMEM_CONV);

    copy_x3_kernel<<<(unsigned)((XELEMS / 4 + 255) / 256), 256>>>(x);
    transpose_w_kernel<<<(COUT_ * KDIM + 255) / 256, 256>>>(w);
    lfbtab_kernel<<<3, 256>>>();              // conv stays at launch idx 3 (ncu -s 5)

    dim3 g1(3, B_SZ * 24);                    // m fastest -> B reuse in L2
    conv_gemm_kernel<<<g1, 256, SMEM_CONV>>>();

    dim3 g2(2, HO_, B_SZ);
    wta_lfb_kernel<<<g2, 256>>>(out);
}

// round 11
// speedup vs baseline: 1.2695x; 1.0849x over previous
#include <cuda_runtime.h>
#include <cstdint>
#include <cfloat>

// ---------------------------------------------------------------------------
// HebbianConv2d (sm_103 baseline ISA):
//   conv as implicit GEMM on mma.sync.m16n8k16.bf16, 3-way bf16 split
//   (6 products, fp32-grade values). WTA winners decided by a hybrid:
//   near-tie pixels (gap < tau) are re-resolved with a sequential fp32
//   fmaf chain bitwise-identical to the proven FFMA kernel (R7), so the
//   winner set matches the reference. Gaussian LFB gating via table.
// ---------------------------------------------------------------------------

#define B_SZ   16
#define CIN_   256
#define COUT_  384
#define HIN_   56
#define HO_    54
#define KDIM   2304                  // 256*9
#define IMG_N  3072                  // padded local-n per image
#define NPAD   (B_SZ * IMG_N)
#define IMG_SZ (CIN_ * HIN_ * HIN_)  // 802816
#define XELEMS ((size_t)B_SZ * IMG_SZ)   // 12,845,056
#define XPW    (XELEMS + 4096)       // per pair-buffer words (+slack)
#define NSTG   144                   // k16 stages
#define AWORDS (3 * NSTG * 3 * 1024) // A packed words: 1,327,104
#define TAU    2e-3f                 // near-tie refinement threshold

__device__ uint32_t g_bp[9 * XPW];              // 9 paired-bf16 streams
__device__ uint32_t g_wA[AWORDS];               // A fragments, bf16-pair packed
__device__ float    g_y[(size_t)NPAD * COUT_];  // pixel-major [padded n][m]
__device__ float    g_lfbtab[768];

__device__ __forceinline__ uint32_t smem_u32(const void* p) {
    uint32_t a;
    asm("{ .reg .u64 t; cvta.to.shared.u64 t, %1; cvt.u32.u64 %0, t; }"
        : "=r"(a) : "l"(p));
    return a;
}
__device__ __forceinline__ void cp16(uint32_t dst, const void* src) {
    asm volatile("cp.async.cg.shared.global [%0], [%1], 16;"
                 :: "r"(dst), "l"(src) : "memory");
}
#define CP_COMMIT() asm volatile("cp.async.commit_group;" ::: "memory")
#define CP_WAIT1()  asm volatile("cp.async.wait_group 1;" ::: "memory")

// bf16 round-to-nearest-even via integer ops
__device__ __forceinline__ float bf16_rn(float x) {
    uint32_t u = __float_as_uint(x);
    u = (u + 0x7fffu + ((u >> 16) & 1u)) & 0xffff0000u;
    return __uint_as_float(u);
}
__device__ __forceinline__ void split3(float x, uint32_t t16[3]) {
    float b0 = bf16_rn(x);  float r1 = x - b0;
    float b1 = bf16_rn(r1); float r2 = r1 - b1;
    float b2 = bf16_rn(r2);
    t16[0] = __float_as_uint(b0) >> 16;
    t16[1] = __float_as_uint(b1) >> 16;
    t16[2] = __float_as_uint(b2) >> 16;
}

__device__ __forceinline__ void mma_bf16(float* d, uint4 a, uint32_t b0, uint32_t b1) {
    asm volatile(
        "mma.sync.aligned.m16n8k16.row.col.f32.bf16.bf16.f32 "
        "{%0,%1,%2,%3}, {%4,%5,%6,%7}, {%8,%9}, {%0,%1,%2,%3};"
        : "+f"(d[0]), "+f"(d[1]), "+f"(d[2]), "+f"(d[3])
        : "r"(a.x), "r"(a.y), "r"(a.z), "r"(a.w), "r"(b0), "r"(b1));
}

// ---------------------------------------------------------------------------
// Prep 1: 9 paired-bf16 streams (3 split terms x 3 pair patterns)
// ---------------------------------------------------------------------------
__global__ void split_pack_kernel(const float* __restrict__ x) {
    size_t u = (size_t)blockIdx.x * 256 + threadIdx.x;
    size_t base = u * 4;
    if (base >= XELEMS) return;

    float v0[6], v58[4], v3k[4];
#pragma unroll
    for (int e = 0; e < 6; e++) {
        size_t i = base + e; if (i > XELEMS - 1) i = XELEMS - 1;
        v0[e] = x[i];
    }
#pragma unroll
    for (int e = 0; e < 4; e++) {
        size_t i = base + 58 + e;   if (i > XELEMS - 1) i = XELEMS - 1;
        v58[e] = x[i];
        i = base + 3138 + e;        if (i > XELEMS - 1) i = XELEMS - 1;
        v3k[e] = x[i];
    }
    uint32_t s0[6][3], s58[4][3], s3k[4][3];
#pragma unroll
    for (int e = 0; e < 6; e++) split3(v0[e], s0[e]);
#pragma unroll
    for (int e = 0; e < 4; e++) { split3(v58[e], s58[e]); split3(v3k[e], s3k[e]); }

#pragma unroll
    for (int t = 0; t < 3; t++) {
        uint4 w0, w1, w2;
        uint32_t* p0 = (uint32_t*)&w0; uint32_t* p1 = (uint32_t*)&w1;
        uint32_t* p2 = (uint32_t*)&w2;
#pragma unroll
        for (int j = 0; j < 4; j++) {
            p0[j] = s0[j][t]     | (s0[j + 1][t] << 16);
            p1[j] = s0[j + 2][t] | (s58[j][t]    << 16);
            p2[j] = s0[j + 2][t] | (s3k[j][t]    << 16);
        }
        ((uint4*)(g_bp + (size_t)(t * 3 + 0) * XPW))[u] = w0;
        ((uint4*)(g_bp + (size_t)(t * 3 + 1) * XPW))[u] = w1;
        ((uint4*)(g_bp + (size_t)(t * 3 + 2) * XPW))[u] = w2;
    }
}

__device__ __forceinline__ int pair_korig(int q, int e) {
    if (q < 1024) {
        int ci = q >> 2, j = q & 3;
        return (j < 3) ? ci * 9 + j * 3 + e : ci * 9 + e * 3 + 2;
    }
    return ((q - 1024) * 2 + e) * 9 + 8;
}

// ---------------------------------------------------------------------------
// Prep 2: A fragments (bf16-pair packed per split term)
// ---------------------------------------------------------------------------
__global__ void wprep_kernel(const float* __restrict__ w) {
    int o = blockIdx.x * 256 + threadIdx.x;
    if (o >= AWORDS) return;
    int r = o & 3, lane = (o >> 2) & 31, f = (o >> 7) & 7;
    int blk = o >> 10;
    int t = blk % 3; int ms = blk / 3; int s = ms % NSTG; int mt = ms / NSTG;
    int g = lane >> 2, tig = lane & 3;
    int m = mt * 128 + f * 16 + g + ((r & 1) ? 8 : 0);
    int q = s * 8 + tig + ((r & 2) ? 4 : 0);
    uint32_t wbits = 0;
#pragma unroll
    for (int e = 0; e < 2; e++) {
        int korig = pair_korig(q, e);
        uint32_t s3[3];
        split3(w[(size_t)m * KDIM + korig], s3);
        wbits |= s3[t] << (16 * e);
    }
    g_wA[o] = wbits;
}

__global__ void lfbtab_kernel() {
    int i = blockIdx.x * 256 + threadIdx.x;
    if (i < 768) {
        int d = i - 383;
        float v = 0.0f;
        if (d >= -191 && d <= 192)
            v = expf(-(float)(d * d) / (2.0f * 191.0f * 191.0f));
        g_lfbtab[i] = v;
    }
}

// ---------------------------------------------------------------------------
// Conv GEMM (bf16 6-term): CTA 128m x 128n, warp 64m x 32n, KS=16.
// ---------------------------------------------------------------------------
#define SLOT_B    25344
#define SMEM_CONV (3 * SLOT_B + 256)

__global__ __launch_bounds__(256, 2)
void conv_mma_kernel()
{
    extern __shared__ char smem[];
    const uint32_t sb = smem_u32(smem);

    const int tid  = threadIdx.x;
    const int lane = tid & 31;
    const int wid  = tid >> 5;
    const int gid  = lane >> 2;
    const int tig  = lane & 3;
    const int wm   = wid & 1;
    const int wn   = wid >> 1;

    const int mt   = blockIdx.x;
    const int m0   = mt * 128;
    const int bimg = blockIdx.y / 24;
    const int nl0  = (blockIdx.y - bimg * 24) * 128;
    const int imgb = bimg * IMG_SZ;

    float d[4][4][4];
#pragma unroll
    for (int i = 0; i < 4; i++)
#pragma unroll
        for (int j = 0; j < 4; j++)
#pragma unroll
            for (int q = 0; q < 4; q++) d[i][j][q] = 0.0f;

    auto issue_stage = [&](int s, int slot) {
        const uint32_t sa = sb + slot * SLOT_B;
        const uint32_t* asrc = g_wA + (size_t)(mt * NSTG + s) * 3072;
#pragma unroll
        for (int j = 0; j < 3; j++) {
            int c = j * 256 + tid;
            cp16(sa + c * 16, asrc + c * 4);
        }
#pragma unroll
        for (int j = 0; j < 3; j++) {
            int idx = j * 256 + tid;
            int t = idx >> 8, row = (idx >> 5) & 7, cin = idx & 31;
            int q = s * 8 + row;
            int typ, boff;
            if (q < 1024) {
                int ci = q >> 2, jj = q & 3;
                if (jj < 3) { typ = 0; boff = ci * 3136 + jj * 56; }
                else        { typ = 1; boff = ci * 3136; }
            } else { typ = 2; boff = (q - 1024) * 2 * 3136 + 112; }
            const uint32_t* src = g_bp + (size_t)(t * 3 + typ) * XPW
                                + imgb + boff + nl0 + cin * 4;
            cp16(sa + 12288 + t * 4352 + row * 544 + cin * 16, src);
        }
        CP_COMMIT();
    };

    auto compute_stage = [&](int slot) {
        const char* base = smem + slot * SLOT_B;
        const char* Bb = base + 12288;
        uint32_t bfr[3][4][2];
#pragma unroll
        for (int t = 0; t < 3; t++) {
            const char* bt = Bb + t * 4352;
#pragma unroll
            for (int nf = 0; nf < 4; nf++) {
                int nw = (wn * 32 + nf * 8 + gid) * 4;
                bfr[t][nf][0] = *(const uint32_t*)(bt + tig * 544 + nw);
                bfr[t][nf][1] = *(const uint32_t*)(bt + (tig + 4) * 544 + nw);
            }
        }
#pragma unroll
        for (int fh = 0; fh < 2; fh++) {
#pragma unroll
            for (int ta = 0; ta < 3; ta++) {
                uint4 afr[2];
#pragma unroll
                for (int f2 = 0; f2 < 2; f2++) {
                    int f = wm * 4 + fh * 2 + f2;
                    afr[f2] = *(const uint4*)(base + ta * 4096 + f * 512 + lane * 16);
                }
                const int ntb = (ta == 0) ? 3 : ((ta == 1) ? 2 : 1);
#pragma unroll
                for (int tb = 0; tb < 3; tb++) {
                    if (tb < ntb) {
#pragma unroll
                        for (int f2 = 0; f2 < 2; f2++)
#pragma unroll
                            for (int nf = 0; nf < 4; nf++)
                                mma_bf16(d[fh * 2 + f2][nf], afr[f2],
                                         bfr[tb][nf][0], bfr[tb][nf][1]);
                    }
                }
            }
        }
    };

    issue_stage(0, 0);
    issue_stage(1, 1);
    for (int s = 0; s < NSTG; s++) {
        CP_WAIT1();
        __syncthreads();
        if (s + 2 < NSTG) issue_stage(s + 2, (s + 2) % 3);
        else CP_COMMIT();
        compute_stage(s % 3);
    }

    // ---- epilogue: D -> smem [n][140] -> coalesced g_y[n][m] ----
    __syncthreads();
    float* ds = (float*)smem;
#pragma unroll
    for (int fm = 0; fm < 4; fm++) {
#pragma unroll
        for (int nf = 0; nf < 4; nf++) {
            int mb = wm * 64 + fm * 16 + gid;
            int nb = wn * 32 + nf * 8 + 2 * tig;
            ds[nb * 140 + mb]           = d[fm][nf][0];
            ds[(nb + 1) * 140 + mb]     = d[fm][nf][1];
            ds[nb * 140 + mb + 8]       = d[fm][nf][2];
            ds[(nb + 1) * 140 + mb + 8] = d[fm][nf][3];
        }
    }
    __syncthreads();
    const int n0g = bimg * IMG_N + nl0;
#pragma unroll
    for (int q = 0; q < 16; q++) {
        int idx = q * 256 + tid;
        int n  = idx >> 5;
        int m4 = idx & 31;
        float4 v = *(const float4*)(ds + n * 140 + m4 * 4);
        *(float4*)(g_y + (size_t)(n0g + n) * COUT_ + m0 + m4 * 4) = v;
    }
}

// ---------------------------------------------------------------------------
// Exact fp32 re-evaluation of one channel's activation, bitwise-identical to
// the proven FFMA kernel (sequential k = ci,kh,kw; fmaf chain).
// ---------------------------------------------------------------------------
__device__ float refine_dot(const float* __restrict__ x, const float* __restrict__ w,
                            int b, int h, int wp, int c) {
    const float* wr = w + (size_t)c * KDIM;
    const float* xb = x + ((size_t)b * CIN_) * (HIN_ * HIN_) + h * HIN_ + wp;
    float acc = 0.0f;
    for (int ci = 0; ci < CIN_; ci++) {
        const float* xr = xb + ci * (HIN_ * HIN_);
        const float* wc = wr + ci * 9;
#pragma unroll
        for (int kh = 0; kh < 3; kh++)
#pragma unroll
            for (int kw = 0; kw < 3; kw++)
                acc = fmaf(xr[kh * HIN_ + kw], wc[kh * 3 + kw], acc);
    }
    return acc;
}

// ---------------------------------------------------------------------------
// WTA + Gaussian LFB gating (27 pixels/block) with near-tie refinement
// ---------------------------------------------------------------------------
#define SYP 388

__global__ __launch_bounds__(256)
void wta_lfb_kernel(const float* __restrict__ xg, const float* __restrict__ wg,
                    float* __restrict__ out) {
    __shared__ float sy[27 * SYP];
    __shared__ float stab[768];
    __shared__ int   wcnt[27];
    __shared__ int   wlist[27][4];
    __shared__ int   ccnt[27];
    __shared__ int   cand[27][8];

    const int tid = threadIdx.x;
    const int b   = blockIdx.z;
    const int h   = blockIdx.y;
    const int w0  = blockIdx.x * 27;

    const size_t base = ((size_t)b * IMG_N + h * HIN_ + w0) * COUT_;

    for (int i4 = tid; i4 < 27 * 96; i4 += 256) {
        float4 v = *(const float4*)(g_y + base + (size_t)i4 * 4);
        int j  = i4 / 96;
        int c4 = i4 - j * 96;
        *(float4*)&sy[j * SYP + c4 * 4] = v;
    }
    if (tid < 192) {
        float4 t = *(const float4*)(g_lfbtab + tid * 4);
        *(float4*)&stab[tid * 4] = t;
    }
    if (tid < 27) { wcnt[tid] = 0; ccnt[tid] = 0; }
    __syncthreads();

    const int wd   = tid >> 5;
    const int lane = tid & 31;
    for (int j = wd; j < 27; j += 8) {
        const float* p = &sy[j * SYP];
        float mx = -FLT_MAX;
#pragma unroll
        for (int q = 0; q < 12; q++) mx = fmaxf(mx, p[lane + q * 32]);
#pragma unroll
        for (int o = 16; o; o >>= 1) mx = fmaxf(mx, __shfl_xor_sync(0xffffffffu, mx, o));
        // candidates within TAU of the max
        const float thr = mx - TAU;
#pragma unroll
        for (int q = 0; q < 12; q++) {
            int c = lane + q * 32;
            if (p[c] >= thr) {
                int pos = atomicAdd(&ccnt[j], 1);
                if (pos < 8) cand[j][pos] = c;
            }
        }
        __syncwarp();
        int nc = ccnt[j]; if (nc > 8) nc = 8;
        if (nc == 1) {
            if (lane == 0) { wlist[j][0] = cand[j][0]; wcnt[j] = 1; }
        } else {
            // near-tie: exact fp32 re-evaluation of each candidate
            float rv = -FLT_MAX;
            if (lane < nc) rv = refine_dot(xg, wg, b, h, w0 + j, cand[j][lane]);
            float rmx = rv;
#pragma unroll
            for (int o = 16; o; o >>= 1) rmx = fmaxf(rmx, __shfl_xor_sync(0xffffffffu, rmx, o));
            if (lane < nc && rv == rmx) {
                int pos = atomicAdd(&wcnt[j], 1);
                if (pos < 4) wlist[j][pos] = cand[j][lane];
            }
        }
    }
    __syncthreads();

    int c = tid / 27;
    int j = tid - c * 27;
    const size_t obase = (((size_t)b * COUT_) * HO_ + h) * HO_ + w0;
    while (c < COUT_) {
        float yv = sy[j * SYP + c];
        int nw = wcnt[j];
        float lfb = stab[wlist[j][0] - c + 383];
        if (nw > 1) {
            if (nw > 4) nw = 4;
            for (int t = 1; t < nw; t++)
                lfb += stab[wlist[j][t] - c + 383];
            lfb = fminf(lfb, 1.0f);
        }
        out[obase + (size_t)c * (HO_ * HO_) + j] = lfb * yv;
        c += 9; j += 13;
        if (j >= 27) { j -= 27; c += 1; }
    }
}

// ---------------------------------------------------------------------------
extern "C" void kernel_launch(void* const* d_in, const int* in_sizes, int n_in,
                              void* d_out, int out_size) {
    const float* x = (const float*)d_in[0];   // (16,256,56,56)
    const float* w = (const float*)d_in[1];   // (384,256,3,3)
    float* out = (float*)d_out;               // (16,384,54,54)

    cudaFuncSetAttribute(conv_mma_kernel,
                         cudaFuncAttributeMaxDynamicSharedMemorySize, SMEM_CONV);

    split_pack_kernel<<<(unsigned)((XELEMS / 4 + 255) / 256), 256>>>(x);
    wprep_kernel<<<(AWORDS + 255) / 256, 256>>>(w);
    lfbtab_kernel<<<3, 256>>>();              // conv at launch idx 3 (ncu -s 5)

    dim3 g1(3, B_SZ * 24);                    // m fastest -> B reuse in L2
    conv_mma_kernel<<<g1, 256, SMEM_CONV>>>();

    dim3 g2(2, HO_, B_SZ);
    wta_lfb_kernel<<<g2, 256>>>(x, w, out);
}

// round 13
// speedup vs baseline: 2.0052x; 1.5796x over previous
#include <cuda_runtime.h>
#include <cstdint>
#include <cfloat>

// ---------------------------------------------------------------------------
// HebbianConv2d (sm_103 baseline ISA):
//   conv as implicit GEMM on mma.sync.m16n8k16.bf16, 2-way bf16 split
//   (3 products: a0b0 + a0b1 + a1b0, residual ~2^-18 -> value error ~4e-6).
//   WTA winners decided by hybrid: near-tie pixels re-resolved with an exact
//   sequential fp32 fmaf chain (matches reference winner set, proven in R11).
//   R12 crash fixed: epilogue stages the 128x128 D tile in smem (71,680 B),
//   so the dynamic smem allocation must cover it, not just the 3 slots.
// ---------------------------------------------------------------------------

#define B_SZ   16
#define CIN_   256
#define COUT_  384
#define HIN_   56
#define HO_    54
#define KDIM   2304                  // 256*9
#define IMG_N  3072                  // padded local-n per image
#define NPAD   (B_SZ * IMG_N)
#define IMG_SZ (CIN_ * HIN_ * HIN_)  // 802816
#define XELEMS ((size_t)B_SZ * IMG_SZ)   // 12,845,056
#define XPW    (XELEMS + 4096)       // per pair-buffer words (+slack)
#define NSTG   144                   // k16 stages
#define AWORDS (3 * NSTG * 2 * 1024) // A packed words: 884,736
#define TAU    2e-3f                 // near-tie refinement threshold

__device__ uint32_t g_bp[6 * XPW];              // 6 paired-bf16 streams
__device__ uint32_t g_wA[AWORDS];               // A fragments, bf16-pair packed
__device__ float    g_y[(size_t)NPAD * COUT_];  // pixel-major [padded n][m]
__device__ float    g_lfbtab[768];

__device__ __forceinline__ uint32_t smem_u32(const void* p) {
    uint32_t a;
    asm("{ .reg .u64 t; cvta.to.shared.u64 t, %1; cvt.u32.u64 %0, t; }"
        : "=r"(a) : "l"(p));
    return a;
}
__device__ __forceinline__ void cp16(uint32_t dst, const void* src) {
    asm volatile("cp.async.cg.shared.global [%0], [%1], 16;"
                 :: "r"(dst), "l"(src) : "memory");
}
#define CP_COMMIT() asm volatile("cp.async.commit_group;" ::: "memory")
#define CP_WAIT1()  asm volatile("cp.async.wait_group 1;" ::: "memory")

// bf16 round-to-nearest-even via integer ops
__device__ __forceinline__ float bf16_rn(float x) {
    uint32_t u = __float_as_uint(x);
    u = (u + 0x7fffu + ((u >> 16) & 1u)) & 0xffff0000u;
    return __uint_as_float(u);
}
// 2-way bf16 split: x ~= b0 + b1, residual ~2^-18 |x|
__device__ __forceinline__ void split2(float x, uint32_t t16[2]) {
    float b0 = bf16_rn(x);
    float b1 = bf16_rn(x - b0);
    t16[0] = __float_as_uint(b0) >> 16;
    t16[1] = __float_as_uint(b1) >> 16;
}

__device__ __forceinline__ void mma_bf16(float* d, uint4 a, uint32_t b0, uint32_t b1) {
    asm volatile(
        "mma.sync.aligned.m16n8k16.row.col.f32.bf16.bf16.f32 "
        "{%0,%1,%2,%3}, {%4,%5,%6,%7}, {%8,%9}, {%0,%1,%2,%3};"
        : "+f"(d[0]), "+f"(d[1]), "+f"(d[2]), "+f"(d[3])
        : "r"(a.x), "r"(a.y), "r"(a.z), "r"(a.w), "r"(b0), "r"(b1));
}

// ---------------------------------------------------------------------------
// Prep 1: 6 paired-bf16 streams (2 split terms x 3 pair patterns)
// ---------------------------------------------------------------------------
__global__ void split_pack_kernel(const float* __restrict__ x) {
    size_t u = (size_t)blockIdx.x * 256 + threadIdx.x;
    size_t base = u * 4;
    if (base >= XELEMS) return;

    float v0[6], v58[4], v3k[4];
#pragma unroll
    for (int e = 0; e < 6; e++) {
        size_t i = base + e; if (i > XELEMS - 1) i = XELEMS - 1;
        v0[e] = x[i];
    }
#pragma unroll
    for (int e = 0; e < 4; e++) {
        size_t i = base + 58 + e;   if (i > XELEMS - 1) i = XELEMS - 1;
        v58[e] = x[i];
        i = base + 3138 + e;        if (i > XELEMS - 1) i = XELEMS - 1;
        v3k[e] = x[i];
    }
    uint32_t s0[6][2], s58[4][2], s3k[4][2];
#pragma unroll
    for (int e = 0; e < 6; e++) split2(v0[e], s0[e]);
#pragma unroll
    for (int e = 0; e < 4; e++) { split2(v58[e], s58[e]); split2(v3k[e], s3k[e]); }

#pragma unroll
    for (int t = 0; t < 2; t++) {
        uint4 w0, w1, w2;
        uint32_t* p0 = (uint32_t*)&w0; uint32_t* p1 = (uint32_t*)&w1;
        uint32_t* p2 = (uint32_t*)&w2;
#pragma unroll
        for (int j = 0; j < 4; j++) {
            p0[j] = s0[j][t]     | (s0[j + 1][t] << 16);
            p1[j] = s0[j + 2][t] | (s58[j][t]    << 16);
            p2[j] = s0[j + 2][t] | (s3k[j][t]    << 16);
        }
        ((uint4*)(g_bp + (size_t)(t * 3 + 0) * XPW))[u] = w0;
        ((uint4*)(g_bp + (size_t)(t * 3 + 1) * XPW))[u] = w1;
        ((uint4*)(g_bp + (size_t)(t * 3 + 2) * XPW))[u] = w2;
    }
}

__device__ __forceinline__ int pair_korig(int q, int e) {
    if (q < 1024) {
        int ci = q >> 2, j = q & 3;
        return (j < 3) ? ci * 9 + j * 3 + e : ci * 9 + e * 3 + 2;
    }
    return ((q - 1024) * 2 + e) * 9 + 8;
}

// ---------------------------------------------------------------------------
// Prep 2: A fragments. word o = ((mt*144+s)*2+t)*1024 + f*128 + lane*4 + r
// ---------------------------------------------------------------------------
__global__ void wprep_kernel(const float* __restrict__ w) {
    int o = blockIdx.x * 256 + threadIdx.x;
    if (o >= AWORDS) return;
    int r = o & 3, lane = (o >> 2) & 31, f = (o >> 7) & 7;
    int blk = o >> 10;
    int t = blk & 1; int ms = blk >> 1; int s = ms % NSTG; int mt = ms / NSTG;
    int g = lane >> 2, tig = lane & 3;
    int m = mt * 128 + f * 16 + g + ((r & 1) ? 8 : 0);
    int q = s * 8 + tig + ((r & 2) ? 4 : 0);
    uint32_t wbits = 0;
#pragma unroll
    for (int e = 0; e < 2; e++) {
        int korig = pair_korig(q, e);
        uint32_t s2[2];
        split2(w[(size_t)m * KDIM + korig], s2);
        wbits |= s2[t] << (16 * e);
    }
    g_wA[o] = wbits;
}

__global__ void lfbtab_kernel() {
    int i = blockIdx.x * 256 + threadIdx.x;
    if (i < 768) {
        int d = i - 383;
        float v = 0.0f;
        if (d >= -191 && d <= 192)
            v = expf(-(float)(d * d) / (2.0f * 191.0f * 191.0f));
        g_lfbtab[i] = v;
    }
}

// ---------------------------------------------------------------------------
// Conv GEMM (bf16 3-term): CTA 128m x 128n, warp 64m x 32n, KS=16.
// Slot: A 2t x 4096B | B 2t x (8 rows x 544B) = 16896B; 3 slots = 50688B.
// Epilogue D staging needs 128*140*4 = 71680B -> smem sized to cover it.
// ---------------------------------------------------------------------------
#define SLOT_B    16896
#define SMEM_CONV 71936                         // max(3*SLOT_B, 128*140*4)+pad

__global__ __launch_bounds__(256, 2)
void conv_mma_kernel()
{
    extern __shared__ char smem[];
    const uint32_t sb = smem_u32(smem);

    const int tid  = threadIdx.x;
    const int lane = tid & 31;
    const int wid  = tid >> 5;
    const int gid  = lane >> 2;
    const int tig  = lane & 3;
    const int wm   = wid & 1;
    const int wn   = wid >> 1;

    const int mt   = blockIdx.x;
    const int m0   = mt * 128;
    const int bimg = blockIdx.y / 24;
    const int nl0  = (blockIdx.y - bimg * 24) * 128;
    const int imgb = bimg * IMG_SZ;

    float d[4][4][4];
#pragma unroll
    for (int i = 0; i < 4; i++)
#pragma unroll
        for (int j = 0; j < 4; j++)
#pragma unroll
            for (int q = 0; q < 4; q++) d[i][j][q] = 0.0f;

    auto issue_stage = [&](int s, int slot) {
        const uint32_t sa = sb + slot * SLOT_B;
        const uint32_t* asrc = g_wA + (size_t)(mt * NSTG + s) * 2048;
#pragma unroll
        for (int j = 0; j < 2; j++) {           // A: 512 chunks
            int c = j * 256 + tid;
            cp16(sa + c * 16, asrc + c * 4);
        }
#pragma unroll
        for (int j = 0; j < 2; j++) {           // B: 512 chunks
            int idx = j * 256 + tid;
            int t = idx >> 8, row = (idx >> 5) & 7, cin = idx & 31;
            int q = s * 8 + row;
            int typ, boff;
            if (q < 1024) {
                int ci = q >> 2, jj = q & 3;
                if (jj < 3) { typ = 0; boff = ci * 3136 + jj * 56; }
                else        { typ = 1; boff = ci * 3136; }
            } else { typ = 2; boff = (q - 1024) * 2 * 3136 + 112; }
            const uint32_t* src = g_bp + (size_t)(t * 3 + typ) * XPW
                                + imgb + boff + nl0 + cin * 4;
            cp16(sa + 8192 + t * 4352 + row * 544 + cin * 16, src);
        }
        CP_COMMIT();
    };

    auto compute_stage = [&](int slot) {
        const char* base = smem + slot * SLOT_B;
        const char* Bb = base + 8192;
        uint32_t bfr[2][4][2];
#pragma unroll
        for (int t = 0; t < 2; t++) {
            const char* bt = Bb + t * 4352;
#pragma unroll
            for (int nf = 0; nf < 4; nf++) {
                int nw = (wn * 32 + nf * 8 + gid) * 4;
                bfr[t][nf][0] = *(const uint32_t*)(bt + tig * 544 + nw);
                bfr[t][nf][1] = *(const uint32_t*)(bt + (tig + 4) * 544 + nw);
            }
        }
#pragma unroll
        for (int fh = 0; fh < 2; fh++) {
#pragma unroll
            for (int ta = 0; ta < 2; ta++) {
                uint4 afr[2];
#pragma unroll
                for (int f2 = 0; f2 < 2; f2++) {
                    int f = wm * 4 + fh * 2 + f2;
                    afr[f2] = *(const uint4*)(base + ta * 4096 + f * 512 + lane * 16);
                }
                const int ntb = (ta == 0) ? 2 : 1;   // (0,0),(0,1),(1,0)
#pragma unroll
                for (int tb = 0; tb < 2; tb++) {
                    if (tb < ntb) {
#pragma unroll
                        for (int f2 = 0; f2 < 2; f2++)
#pragma unroll
                            for (int nf = 0; nf < 4; nf++)
                                mma_bf16(d[fh * 2 + f2][nf], afr[f2],
                                         bfr[tb][nf][0], bfr[tb][nf][1]);
                    }
                }
            }
        }
    };

    issue_stage(0, 0);
    issue_stage(1, 1);
    for (int s = 0; s < NSTG; s++) {
        CP_WAIT1();
        __syncthreads();
        if (s + 2 < NSTG) issue_stage(s + 2, (s + 2) % 3);
        else CP_COMMIT();
        compute_stage(s % 3);
    }

    // ---- epilogue: D -> smem [n][140] -> coalesced g_y[n][m] ----
    __syncthreads();
    float* ds = (float*)smem;
#pragma unroll
    for (int fm = 0; fm < 4; fm++) {
#pragma unroll
        for (int nf = 0; nf < 4; nf++) {
            int mb = wm * 64 + fm * 16 + gid;
            int nb = wn * 32 + nf * 8 + 2 * tig;
            ds[nb * 140 + mb]           = d[fm][nf][0];
            ds[(nb + 1) * 140 + mb]     = d[fm][nf][1];
            ds[nb * 140 + mb + 8]       = d[fm][nf][2];
            ds[(nb + 1) * 140 + mb + 8] = d[fm][nf][3];
        }
    }
    __syncthreads();
    const int n0g = bimg * IMG_N + nl0;
#pragma unroll
    for (int q = 0; q < 16; q++) {
        int idx = q * 256 + tid;
        int n  = idx >> 5;
        int m4 = idx & 31;
        float4 v = *(const float4*)(ds + n * 140 + m4 * 4);
        *(float4*)(g_y + (size_t)(n0g + n) * COUT_ + m0 + m4 * 4) = v;
    }
}

// ---------------------------------------------------------------------------
// Exact fp32 re-evaluation (sequential k = ci,kh,kw; fmaf chain)
// ---------------------------------------------------------------------------
__device__ float refine_dot(const float* __restrict__ x, const float* __restrict__ w,
                            int b, int h, int wp, int c) {
    const float* wr = w + (size_t)c * KDIM;
    const float* xb = x + ((size_t)b * CIN_) * (HIN_ * HIN_) + h * HIN_ + wp;
    float acc = 0.0f;
    for (int ci = 0; ci < CIN_; ci++) {
        const float* xr = xb + ci * (HIN_ * HIN_);
        const float* wc = wr + ci * 9;
#pragma unroll
        for (int kh = 0; kh < 3; kh++)
#pragma unroll
            for (int kw = 0; kw < 3; kw++)
                acc = fmaf(xr[kh * HIN_ + kw], wc[kh * 3 + kw], acc);
    }
    return acc;
}

// ---------------------------------------------------------------------------
// WTA + Gaussian LFB gating (27 pixels/block) with near-tie refinement
// ---------------------------------------------------------------------------
#define SYP 388

__global__ __launch_bounds__(256)
void wta_lfb_kernel(const float* __restrict__ xg, const float* __restrict__ wg,
                    float* __restrict__ out) {
    __shared__ float sy[27 * SYP];
    __shared__ float stab[768];
    __shared__ int   wcnt[27];
    __shared__ int   wlist[27][4];
    __shared__ int   ccnt[27];
    __shared__ int   cand[27][8];

    const int tid = threadIdx.x;
    const int b   = blockIdx.z;
    const int h   = blockIdx.y;
    const int w0  = blockIdx.x * 27;

    const size_t base = ((size_t)b * IMG_N + h * HIN_ + w0) * COUT_;

    for (int i4 = tid; i4 < 27 * 96; i4 += 256) {
        float4 v = *(const float4*)(g_y + base + (size_t)i4 * 4);
        int j  = i4 / 96;
        int c4 = i4 - j * 96;
        *(float4*)&sy[j * SYP + c4 * 4] = v;
    }
    if (tid < 192) {
        float4 t = *(const float4*)(g_lfbtab + tid * 4);
        *(float4*)&stab[tid * 4] = t;
    }
    if (tid < 27) { wcnt[tid] = 0; ccnt[tid] = 0; }
    __syncthreads();

    const int wd   = tid >> 5;
    const int lane = tid & 31;
    for (int j = wd; j < 27; j += 8) {
        const float* p = &sy[j * SYP];
        float mx = -FLT_MAX;
#pragma unroll
        for (int q = 0; q < 12; q++) mx = fmaxf(mx, p[lane + q * 32]);
#pragma unroll
        for (int o = 16; o; o >>= 1) mx = fmaxf(mx, __shfl_xor_sync(0xffffffffu, mx, o));
        const float thr = mx - TAU;
#pragma unroll
        for (int q = 0; q < 12; q++) {
            int c = lane + q * 32;
            if (p[c] >= thr) {
                int pos = atomicAdd(&ccnt[j], 1);
                if (pos < 8) cand[j][pos] = c;
            }
        }
        __syncwarp();
        int nc = ccnt[j]; if (nc > 8) nc = 8;
        if (nc == 1) {
            if (lane == 0) { wlist[j][0] = cand[j][0]; wcnt[j] = 1; }
        } else {
            float rv = -FLT_MAX;
            if (lane < nc) rv = refine_dot(xg, wg, b, h, w0 + j, cand[j][lane]);
            float rmx = rv;
#pragma unroll
            for (int o = 16; o; o >>= 1) rmx = fmaxf(rmx, __shfl_xor_sync(0xffffffffu, rmx, o));
            if (lane < nc && rv == rmx) {
                int pos = atomicAdd(&wcnt[j], 1);
                if (pos < 4) wlist[j][pos] = cand[j][lane];
            }
        }
    }
    __syncthreads();

    int c = tid / 27;
    int j = tid - c * 27;
    const size_t obase = (((size_t)b * COUT_) * HO_ + h) * HO_ + w0;
    while (c < COUT_) {
        float yv = sy[j * SYP + c];
        int nw = wcnt[j];
        float lfb = stab[wlist[j][0] - c + 383];
        if (nw > 1) {
            if (nw > 4) nw = 4;
            for (int t = 1; t < nw; t++)
                lfb += stab[wlist[j][t] - c + 383];
            lfb = fminf(lfb, 1.0f);
        }
        out[obase + (size_t)c * (HO_ * HO_) + j] = lfb * yv;
        c += 9; j += 13;
        if (j >= 27) { j -= 27; c += 1; }
    }
}

// ---------------------------------------------------------------------------
extern "C" void kernel_launch(void* const* d_in, const int* in_sizes, int n_in,
                              void* d_out, int out_size) {
    const float* x = (const float*)d_in[0];   // (16,256,56,56)
    const float* w = (const float*)d_in[1];   // (384,256,3,3)
    float* out = (float*)d_out;               // (16,384,54,54)

    cudaFuncSetAttribute(conv_mma_kernel,
                         cudaFuncAttributeMaxDynamicSharedMemorySize, SMEM_CONV);

    split_pack_kernel<<<(unsigned)((XELEMS / 4 + 255) / 256), 256>>>(x);
    wprep_kernel<<<(AWORDS + 255) / 256, 256>>>(w);
    lfbtab_kernel<<<3, 256>>>();              // conv at launch idx 3 (ncu -s 5)

    dim3 g1(3, B_SZ * 24);                    // m fastest -> B reuse in L2
    conv_mma_kernel<<<g1, 256, SMEM_CONV>>>();

    dim3 g2(2, HO_, B_SZ);
    wta_lfb_kernel<<<g2, 256>>>(x, w, out);
}

// round 14
// speedup vs baseline: 2.0402x; 1.0174x over previous
#include <cuda_runtime.h>
#include <cstdint>
#include <cfloat>

// ---------------------------------------------------------------------------
// HebbianConv2d (sm_103 baseline ISA):
//   conv as implicit GEMM on mma.sync.m16n8k16.bf16, 2-way bf16 split
//   (3 products: a0b0 + a0b1 + a1b0). KS=32 stages (2 k16 slabs) halve the
//   barrier count vs R13 to raise tensor-pipe occupancy. WTA winners decided
//   by hybrid near-tie exact fp32 refinement; Gaussian LFB via table.
// ---------------------------------------------------------------------------

#define B_SZ   16
#define CIN_   256
#define COUT_  384
#define HIN_   56
#define HO_    54
#define KDIM   2304                  // 256*9
#define IMG_N  3072                  // padded local-n per image
#define NPAD   (B_SZ * IMG_N)
#define IMG_SZ (CIN_ * HIN_ * HIN_)  // 802816
#define XELEMS ((size_t)B_SZ * IMG_SZ)   // 12,845,056
#define XPW    (XELEMS + 4096)       // per pair-buffer words (+slack)
#define NS144  144                   // old k16 stage count (A-prep layout)
#define NSTG   72                    // KS=32 stages
#define AWORDS (3 * NS144 * 2 * 1024) // A packed words: 884,736
#define TAU    2e-3f                 // near-tie refinement threshold

__device__ uint32_t g_bp[6 * XPW];              // 6 paired-bf16 streams
__device__ uint32_t g_wA[AWORDS];               // A fragments, bf16-pair packed
__device__ float    g_y[(size_t)NPAD * COUT_];  // pixel-major [padded n][m]
__device__ float    g_lfbtab[768];

__device__ __forceinline__ uint32_t smem_u32(const void* p) {
    uint32_t a;
    asm("{ .reg .u64 t; cvta.to.shared.u64 t, %1; cvt.u32.u64 %0, t; }"
        : "=r"(a) : "l"(p));
    return a;
}
__device__ __forceinline__ void cp16(uint32_t dst, const void* src) {
    asm volatile("cp.async.cg.shared.global [%0], [%1], 16;"
                 :: "r"(dst), "l"(src) : "memory");
}
#define CP_COMMIT() asm volatile("cp.async.commit_group;" ::: "memory")
#define CP_WAIT1()  asm volatile("cp.async.wait_group 1;" ::: "memory")

// bf16 round-to-nearest-even via integer ops
__device__ __forceinline__ float bf16_rn(float x) {
    uint32_t u = __float_as_uint(x);
    u = (u + 0x7fffu + ((u >> 16) & 1u)) & 0xffff0000u;
    return __uint_as_float(u);
}
__device__ __forceinline__ void split2(float x, uint32_t t16[2]) {
    float b0 = bf16_rn(x);
    float b1 = bf16_rn(x - b0);
    t16[0] = __float_as_uint(b0) >> 16;
    t16[1] = __float_as_uint(b1) >> 16;
}

__device__ __forceinline__ void mma_bf16(float* d, uint4 a, uint32_t b0, uint32_t b1) {
    asm volatile(
        "mma.sync.aligned.m16n8k16.row.col.f32.bf16.bf16.f32 "
        "{%0,%1,%2,%3}, {%4,%5,%6,%7}, {%8,%9}, {%0,%1,%2,%3};"
        : "+f"(d[0]), "+f"(d[1]), "+f"(d[2]), "+f"(d[3])
        : "r"(a.x), "r"(a.y), "r"(a.z), "r"(a.w), "r"(b0), "r"(b1));
}

// ---------------------------------------------------------------------------
// Prep 1: 6 paired-bf16 streams (2 split terms x 3 pair patterns)
// ---------------------------------------------------------------------------
__global__ void split_pack_kernel(const float* __restrict__ x) {
    size_t u = (size_t)blockIdx.x * 256 + threadIdx.x;
    size_t base = u * 4;
    if (base >= XELEMS) return;

    float v0[6], v58[4], v3k[4];
#pragma unroll
    for (int e = 0; e < 6; e++) {
        size_t i = base + e; if (i > XELEMS - 1) i = XELEMS - 1;
        v0[e] = x[i];
    }
#pragma unroll
    for (int e = 0; e < 4; e++) {
        size_t i = base + 58 + e;   if (i > XELEMS - 1) i = XELEMS - 1;
        v58[e] = x[i];
        i = base + 3138 + e;        if (i > XELEMS - 1) i = XELEMS - 1;
        v3k[e] = x[i];
    }
    uint32_t s0[6][2], s58[4][2], s3k[4][2];
#pragma unroll
    for (int e = 0; e < 6; e++) split2(v0[e], s0[e]);
#pragma unroll
    for (int e = 0; e < 4; e++) { split2(v58[e], s58[e]); split2(v3k[e], s3k[e]); }

#pragma unroll
    for (int t = 0; t < 2; t++) {
        uint4 w0, w1, w2;
        uint32_t* p0 = (uint32_t*)&w0; uint32_t* p1 = (uint32_t*)&w1;
        uint32_t* p2 = (uint32_t*)&w2;
#pragma unroll
        for (int j = 0; j < 4; j++) {
            p0[j] = s0[j][t]     | (s0[j + 1][t] << 16);
            p1[j] = s0[j + 2][t] | (s58[j][t]    << 16);
            p2[j] = s0[j + 2][t] | (s3k[j][t]    << 16);
        }
        ((uint4*)(g_bp + (size_t)(t * 3 + 0) * XPW))[u] = w0;
        ((uint4*)(g_bp + (size_t)(t * 3 + 1) * XPW))[u] = w1;
        ((uint4*)(g_bp + (size_t)(t * 3 + 2) * XPW))[u] = w2;
    }
}

__device__ __forceinline__ int pair_korig(int q, int e) {
    if (q < 1024) {
        int ci = q >> 2, j = q & 3;
        return (j < 3) ? ci * 9 + j * 3 + e : ci * 9 + e * 3 + 2;
    }
    return ((q - 1024) * 2 + e) * 9 + 8;
}

// ---------------------------------------------------------------------------
// Prep 2: A fragments. word o = ((mt*144+s144)*2+t)*1024 + f*128 + lane*4 + r
// ---------------------------------------------------------------------------
__global__ void wprep_kernel(const float* __restrict__ w) {
    int o = blockIdx.x * 256 + threadIdx.x;
    if (o >= AWORDS) return;
    int r = o & 3, lane = (o >> 2) & 31, f = (o >> 7) & 7;
    int blk = o >> 10;
    int t = blk & 1; int ms = blk >> 1; int s = ms % NS144; int mt = ms / NS144;
    int g = lane >> 2, tig = lane & 3;
    int m = mt * 128 + f * 16 + g + ((r & 1) ? 8 : 0);
    int q = s * 8 + tig + ((r & 2) ? 4 : 0);
    uint32_t wbits = 0;
#pragma unroll
    for (int e = 0; e < 2; e++) {
        int korig = pair_korig(q, e);
        uint32_t s2[2];
        split2(w[(size_t)m * KDIM + korig], s2);
        wbits |= s2[t] << (16 * e);
    }
    g_wA[o] = wbits;
}

__global__ void lfbtab_kernel() {
    int i = blockIdx.x * 256 + threadIdx.x;
    if (i < 768) {
        int d = i - 383;
        float v = 0.0f;
        if (d >= -191 && d <= 192)
            v = expf(-(float)(d * d) / (2.0f * 191.0f * 191.0f));
        g_lfbtab[i] = v;
    }
}

// ---------------------------------------------------------------------------
// Conv GEMM (bf16 3-term): CTA 128m x 128n, warp 64m x 32n, KS=32.
// Slot: A 16384B (2 slabs x 2t x 4096) | B 2t x (16 rows x 544B) = 33792B.
// 3 slots = 101376B; epilogue D staging (71680B) fits inside.
// ---------------------------------------------------------------------------
#define SLOT_B    33792
#define SMEM_CONV (3 * SLOT_B)                  // 101376

__global__ __launch_bounds__(256, 2)
void conv_mma_kernel()
{
    extern __shared__ char smem[];
    const uint32_t sb = smem_u32(smem);

    const int tid  = threadIdx.x;
    const int lane = tid & 31;
    const int wid  = tid >> 5;
    const int gid  = lane >> 2;
    const int tig  = lane & 3;
    const int wm   = wid & 1;
    const int wn   = wid >> 1;

    const int mt   = blockIdx.x;
    const int m0   = mt * 128;
    const int bimg = blockIdx.y / 24;
    const int nl0  = (blockIdx.y - bimg * 24) * 128;
    const int imgb = bimg * IMG_SZ;

    float d[4][4][4];
#pragma unroll
    for (int i = 0; i < 4; i++)
#pragma unroll
        for (int j = 0; j < 4; j++)
#pragma unroll
            for (int q = 0; q < 4; q++) d[i][j][q] = 0.0f;

    auto issue_stage = [&](int s, int slot) {
        const uint32_t sa = sb + slot * SLOT_B;
        // A: two consecutive old-stage blocks = 4096 words, flat copy
        const uint32_t* asrc = g_wA + (size_t)(mt * NS144 + s * 2) * 2048;
#pragma unroll
        for (int j = 0; j < 4; j++) {
            int c = j * 256 + tid;
            cp16(sa + c * 16, asrc + c * 4);
        }
        // B: 2t x 16 rows x 32 chunks
#pragma unroll
        for (int j = 0; j < 4; j++) {
            int idx = j * 256 + tid;
            int t = idx >> 9, row = (idx >> 5) & 15, cin = idx & 31;
            int q = s * 16 + row;
            int typ, boff;
            if (q < 1024) {
                int ci = q >> 2, jj = q & 3;
                if (jj < 3) { typ = 0; boff = ci * 3136 + jj * 56; }
                else        { typ = 1; boff = ci * 3136; }
            } else { typ = 2; boff = (q - 1024) * 2 * 3136 + 112; }
            const uint32_t* src = g_bp + (size_t)(t * 3 + typ) * XPW
                                + imgb + boff + nl0 + cin * 4;
            cp16(sa + 16384 + t * 8704 + row * 544 + cin * 16, src);
        }
        CP_COMMIT();
    };

    auto compute_stage = [&](int slot) {
        const char* base = smem + slot * SLOT_B;
        const char* Bb = base + 16384;
#pragma unroll
        for (int slab = 0; slab < 2; slab++) {
            uint32_t bfr[2][4][2];
#pragma unroll
            for (int t = 0; t < 2; t++) {
                const char* bt = Bb + t * 8704 + slab * (8 * 544);
#pragma unroll
                for (int nf = 0; nf < 4; nf++) {
                    int nw = (wn * 32 + nf * 8 + gid) * 4;
                    bfr[t][nf][0] = *(const uint32_t*)(bt + tig * 544 + nw);
                    bfr[t][nf][1] = *(const uint32_t*)(bt + (tig + 4) * 544 + nw);
                }
            }
            const char* Ab = base + slab * 8192;
#pragma unroll
            for (int fh = 0; fh < 2; fh++) {
#pragma unroll
                for (int ta = 0; ta < 2; ta++) {
                    uint4 afr[2];
#pragma unroll
                    for (int f2 = 0; f2 < 2; f2++) {
                        int f = wm * 4 + fh * 2 + f2;
                        afr[f2] = *(const uint4*)(Ab + ta * 4096 + f * 512 + lane * 16);
                    }
                    const int ntb = (ta == 0) ? 2 : 1;   // (0,0),(0,1),(1,0)
#pragma unroll
                    for (int tb = 0; tb < 2; tb++) {
                        if (tb < ntb) {
#pragma unroll
                            for (int f2 = 0; f2 < 2; f2++)
#pragma unroll
                                for (int nf = 0; nf < 4; nf++)
                                    mma_bf16(d[fh * 2 + f2][nf], afr[f2],
                                             bfr[tb][nf][0], bfr[tb][nf][1]);
                        }
                    }
                }
            }
        }
    };

    issue_stage(0, 0);
    issue_stage(1, 1);
    for (int s = 0; s < NSTG; s++) {
        CP_WAIT1();
        __syncthreads();
        if (s + 2 < NSTG) issue_stage(s + 2, (s + 2) % 3);
        else CP_COMMIT();
        compute_stage(s % 3);
    }

    // ---- epilogue: D -> smem [n][140] -> coalesced g_y[n][m] ----
    __syncthreads();
    float* ds = (float*)smem;
#pragma unroll
    for (int fm = 0; fm < 4; fm++) {
#pragma unroll
        for (int nf = 0; nf < 4; nf++) {
            int mb = wm * 64 + fm * 16 + gid;
            int nb = wn * 32 + nf * 8 + 2 * tig;
            ds[nb * 140 + mb]           = d[fm][nf][0];
            ds[(nb + 1) * 140 + mb]     = d[fm][nf][1];
            ds[nb * 140 + mb + 8]       = d[fm][nf][2];
            ds[(nb + 1) * 140 + mb + 8] = d[fm][nf][3];
        }
    }
    __syncthreads();
    const int n0g = bimg * IMG_N + nl0;
#pragma unroll
    for (int q = 0; q < 16; q++) {
        int idx = q * 256 + tid;
        int n  = idx >> 5;
        int m4 = idx & 31;
        float4 v = *(const float4*)(ds + n * 140 + m4 * 4);
        *(float4*)(g_y + (size_t)(n0g + n) * COUT_ + m0 + m4 * 4) = v;
    }
}

// ---------------------------------------------------------------------------
// Exact fp32 re-evaluation (sequential k = ci,kh,kw; fmaf chain)
// ---------------------------------------------------------------------------
__device__ float refine_dot(const float* __restrict__ x, const float* __restrict__ w,
                            int b, int h, int wp, int c) {
    const float* wr = w + (size_t)c * KDIM;
    const float* xb = x + ((size_t)b * CIN_) * (HIN_ * HIN_) + h * HIN_ + wp;
    float acc = 0.0f;
    for (int ci = 0; ci < CIN_; ci++) {
        const float* xr = xb + ci * (HIN_ * HIN_);
        const float* wc = wr + ci * 9;
#pragma unroll
        for (int kh = 0; kh < 3; kh++)
#pragma unroll
            for (int kw = 0; kw < 3; kw++)
                acc = fmaf(xr[kh * HIN_ + kw], wc[kh * 3 + kw], acc);
    }
    return acc;
}

// ---------------------------------------------------------------------------
// WTA + Gaussian LFB gating (27 pixels/block) with near-tie refinement
// ---------------------------------------------------------------------------
#define SYP 388

__global__ __launch_bounds__(256)
void wta_lfb_kernel(const float* __restrict__ xg, const float* __restrict__ wg,
                    float* __restrict__ out) {
    __shared__ float sy[27 * SYP];
    __shared__ float stab[768];
    __shared__ int   wcnt[27];
    __shared__ int   wlist[27][4];
    __shared__ int   ccnt[27];
    __shared__ int   cand[27][8];

    const int tid = threadIdx.x;
    const int b   = blockIdx.z;
    const int h   = blockIdx.y;
    const int w0  = blockIdx.x * 27;

    const size_t base = ((size_t)b * IMG_N + h * HIN_ + w0) * COUT_;

    for (int i4 = tid; i4 < 27 * 96; i4 += 256) {
        float4 v = *(const float4*)(g_y + base + (size_t)i4 * 4);
        int j  = i4 / 96;
        int c4 = i4 - j * 96;
        *(float4*)&sy[j * SYP + c4 * 4] = v;
    }
    if (tid < 192) {
        float4 t = *(const float4*)(g_lfbtab + tid * 4);
        *(float4*)&stab[tid * 4] = t;
    }
    if (tid < 27) { wcnt[tid] = 0; ccnt[tid] = 0; }
    __syncthreads();

    const int wd   = tid >> 5;
    const int lane = tid & 31;
    for (int j = wd; j < 27; j += 8) {
        const float* p = &sy[j * SYP];
        float mx = -FLT_MAX;
#pragma unroll
        for (int q = 0; q < 12; q++) mx = fmaxf(mx, p[lane + q * 32]);
#pragma unroll
        for (int o = 16; o; o >>= 1) mx = fmaxf(mx, __shfl_xor_sync(0xffffffffu, mx, o));
        const float thr = mx - TAU;
#pragma unroll
        for (int q = 0; q < 12; q++) {
            int c = lane + q * 32;
            if (p[c] >= thr) {
                int pos = atomicAdd(&ccnt[j], 1);
                if (pos < 8) cand[j][pos] = c;
            }
        }
        __syncwarp();
        int nc = ccnt[j]; if (nc > 8) nc = 8;
        if (nc == 1) {
            if (lane == 0) { wlist[j][0] = cand[j][0]; wcnt[j] = 1; }
        } else {
            float rv = -FLT_MAX;
            if (lane < nc) rv = refine_dot(xg, wg, b, h, w0 + j, cand[j][lane]);
            float rmx = rv;
#pragma unroll
            for (int o = 16; o; o >>= 1) rmx = fmaxf(rmx, __shfl_xor_sync(0xffffffffu, rmx, o));
            if (lane < nc && rv == rmx) {
                int pos = atomicAdd(&wcnt[j], 1);
                if (pos < 4) wlist[j][pos] = cand[j][lane];
            }
        }
    }
    __syncthreads();

    int c = tid / 27;
    int j = tid - c * 27;
    const size_t obase = (((size_t)b * COUT_) * HO_ + h) * HO_ + w0;
    while (c < COUT_) {
        float yv = sy[j * SYP + c];
        int nw = wcnt[j];
        float lfb = stab[wlist[j][0] - c + 383];
        if (nw > 1) {
            if (nw > 4) nw = 4;
            for (int t = 1; t < nw; t++)
                lfb += stab[wlist[j][t] - c + 383];
            lfb = fminf(lfb, 1.0f);
        }
        out[obase + (size_t)c * (HO_ * HO_) + j] = lfb * yv;
        c += 9; j += 13;
        if (j >= 27) { j -= 27; c += 1; }
    }
}

// ---------------------------------------------------------------------------
extern "C" void kernel_launch(void* const* d_in, const int* in_sizes, int n_in,
                              void* d_out, int out_size) {
    const float* x = (const float*)d_in[0];   // (16,256,56,56)
    const float* w = (const float*)d_in[1];   // (384,256,3,3)
    float* out = (float*)d_out;               // (16,384,54,54)

    cudaFuncSetAttribute(conv_mma_kernel,
                         cudaFuncAttributeMaxDynamicSharedMemorySize, SMEM_CONV);

    split_pack_kernel<<<(unsigned)((XELEMS / 4 + 255) / 256), 256>>>(x);
    wprep_kernel<<<(AWORDS + 255) / 256, 256>>>(w);
    lfbtab_kernel<<<3, 256>>>();              // conv at launch idx 3 (ncu -s 5)

    dim3 g1(3, B_SZ * 24);                    // m fastest -> B reuse in L2
    conv_mma_kernel<<<g1, 256, SMEM_CONV>>>();

    dim3 g2(2, HO_, B_SZ);
    wta_lfb_kernel<<<g2, 256>>>(x, w, out);
}

// round 16
// speedup vs baseline: 2.0744x; 1.0168x over previous
#include <cuda_runtime.h>
#include <cstdint>
#include <cfloat>

// ---------------------------------------------------------------------------
// HebbianConv2d (sm_103 baseline ISA):
//   conv as implicit GEMM on mma.sync.m16n8k16.bf16, 2-way bf16 split
//   (3 products: a0b0 + a0b1 + a1b0). KS=32 stages. TWO k-pair patterns:
//   (i,i+1) and shifted (i+2,i+3138) -- the +2 is baked into the stream so
//   every conv-side cp.async source is 16B-aligned (R15 bug fix). Prep is
//   fully float4-vectorized (4 aligned LDG.128 + 4 STG.128 per thread).
//   WTA winners via hybrid near-tie exact fp32 refinement; LFB via table.
// ---------------------------------------------------------------------------

#define B_SZ   16
#define CIN_   256
#define COUT_  384
#define HIN_   56
#define HO_    54
#define KDIM   2304                  // 256*9
#define IMG_N  3072                  // padded local-n per image
#define NPAD   (B_SZ * IMG_N)
#define IMG_SZ (CIN_ * HIN_ * HIN_)  // 802816
#define XELEMS ((size_t)B_SZ * IMG_SZ)   // 12,845,056
#define XPW    (XELEMS + 4096)       // per pair-buffer words (+slack)
#define NS144  144                   // k16 slab count (A-prep layout)
#define NSTG   72                    // KS=32 stages
#define AWORDS (3 * NS144 * 2 * 1024) // A packed words: 884,736
#define TAU    2e-3f                 // near-tie refinement threshold

__device__ uint32_t g_bp[4 * XPW];              // 4 paired-bf16 streams
__device__ uint32_t g_wA[AWORDS];               // A fragments, bf16-pair packed
__device__ float    g_y[(size_t)NPAD * COUT_];  // pixel-major [padded n][m]
__device__ float    g_lfbtab[768];

__device__ __forceinline__ uint32_t smem_u32(const void* p) {
    uint32_t a;
    asm("{ .reg .u64 t; cvta.to.shared.u64 t, %1; cvt.u32.u64 %0, t; }"
        : "=r"(a) : "l"(p));
    return a;
}
__device__ __forceinline__ void cp16(uint32_t dst, const void* src) {
    asm volatile("cp.async.cg.shared.global [%0], [%1], 16;"
                 :: "r"(dst), "l"(src) : "memory");
}
#define CP_COMMIT() asm volatile("cp.async.commit_group;" ::: "memory")
#define CP_WAIT1()  asm volatile("cp.async.wait_group 1;" ::: "memory")

// bf16 round-to-nearest-even via integer ops
__device__ __forceinline__ float bf16_rn(float x) {
    uint32_t u = __float_as_uint(x);
    u = (u + 0x7fffu + ((u >> 16) & 1u)) & 0xffff0000u;
    return __uint_as_float(u);
}
__device__ __forceinline__ void split2(float x, uint32_t t16[2]) {
    float b0 = bf16_rn(x);
    float b1 = bf16_rn(x - b0);
    t16[0] = __float_as_uint(b0) >> 16;
    t16[1] = __float_as_uint(b1) >> 16;
}

__device__ __forceinline__ void mma_bf16(float* d, uint4 a, uint32_t b0, uint32_t b1) {
    asm volatile(
        "mma.sync.aligned.m16n8k16.row.col.f32.bf16.bf16.f32 "
        "{%0,%1,%2,%3}, {%4,%5,%6,%7}, {%8,%9}, {%0,%1,%2,%3};"
        : "+f"(d[0]), "+f"(d[1]), "+f"(d[2]), "+f"(d[3])
        : "r"(a.x), "r"(a.y), "r"(a.z), "r"(a.w), "r"(b0), "r"(b1));
}

// ---------------------------------------------------------------------------
// k-pair scheme (2 patterns):
//   q < 768 : type0. ci=q/3, j=q%3. pair ((ci,j,0),(ci,j,1));
//             stream0 word i: (x[i], x[i+1]); boff = ci*3136 + j*56
//   q >= 768: type1. p=q-768, cp=p/3, kh=p%3. pair ((2cp,kh,2),(2cp+1,kh,2));
//             stream1 word i: (x[i+2], x[i+3138]); boff = cp*6272 + kh*56
//   Both boffs are multiples of 4 words -> 16B-aligned cp.async sources.
// ---------------------------------------------------------------------------
__device__ __forceinline__ int pair_korig(int q, int e) {
    if (q < 768) { int ci = q / 3, j = q - ci * 3; return ci * 9 + j * 3 + e; }
    int p = q - 768; int cp = p / 3, kh = p - cp * 3;
    return (2 * cp + e) * 9 + kh * 3 + 2;
}

// ---------------------------------------------------------------------------
// Prep 1: 4 paired-bf16 streams, fully vectorized aligned loads.
//   stream (t*2+0): word[i] = pack(t(x[i]),   t(x[i+1]))
//   stream (t*2+1): word[i] = pack(t(x[i+2]), t(x[i+3138]))
// ---------------------------------------------------------------------------
__global__ void split_pack_kernel(const float* __restrict__ x) {
    size_t u = (size_t)blockIdx.x * 256 + threadIdx.x;
    size_t base = u * 4;
    if (base >= XELEMS) return;

    float v0[6], v3k[4];                         // v0[e] = x[base+e] (e=0..5)
    if (base + 3144 <= XELEMS) {                 // fast path: 4 aligned float4
        float4 a = *(const float4*)(x + base);
        float4 b = *(const float4*)(x + base + 4);
        float4 c = *(const float4*)(x + base + 3136);
        float4 e4 = *(const float4*)(x + base + 3140);
        v0[0] = a.x; v0[1] = a.y; v0[2] = a.z; v0[3] = a.w;
        v0[4] = b.x; v0[5] = b.y;
        v3k[0] = c.z; v3k[1] = c.w; v3k[2] = e4.x; v3k[3] = e4.y;  // +3138..3141
    } else {                                     // tail: clamped scalars
#pragma unroll
        for (int e = 0; e < 6; e++) {
            size_t i = base + e; if (i > XELEMS - 1) i = XELEMS - 1;
            v0[e] = x[i];
        }
#pragma unroll
        for (int e = 0; e < 4; e++) {
            size_t i = base + 3138 + e; if (i > XELEMS - 1) i = XELEMS - 1;
            v3k[e] = x[i];
        }
    }
    uint32_t s0[6][2], s3k[4][2];
#pragma unroll
    for (int e = 0; e < 6; e++) split2(v0[e], s0[e]);
#pragma unroll
    for (int e = 0; e < 4; e++) split2(v3k[e], s3k[e]);

#pragma unroll
    for (int t = 0; t < 2; t++) {
        uint4 w0, w2;
        uint32_t* p0 = (uint32_t*)&w0; uint32_t* p2 = (uint32_t*)&w2;
#pragma unroll
        for (int j = 0; j < 4; j++) {
            p0[j] = s0[j][t]     | (s0[j + 1][t] << 16);   // (x[i], x[i+1])
            p2[j] = s0[j + 2][t] | (s3k[j][t]    << 16);   // (x[i+2], x[i+3138])
        }
        ((uint4*)(g_bp + (size_t)(t * 2 + 0) * XPW))[u] = w0;
        ((uint4*)(g_bp + (size_t)(t * 2 + 1) * XPW))[u] = w2;
    }
}

// ---------------------------------------------------------------------------
// Prep 2: A fragments. word o = ((mt*144+s144)*2+t)*1024 + f*128 + lane*4 + r
// ---------------------------------------------------------------------------
__global__ void wprep_kernel(const float* __restrict__ w) {
    int o = blockIdx.x * 256 + threadIdx.x;
    if (o >= AWORDS) return;
    int r = o & 3, lane = (o >> 2) & 31, f = (o >> 7) & 7;
    int blk = o >> 10;
    int t = blk & 1; int ms = blk >> 1; int s = ms % NS144; int mt = ms / NS144;
    int g = lane >> 2, tig = lane & 3;
    int m = mt * 128 + f * 16 + g + ((r & 1) ? 8 : 0);
    int q = s * 8 + tig + ((r & 2) ? 4 : 0);
    uint32_t wbits = 0;
#pragma unroll
    for (int e = 0; e < 2; e++) {
        int korig = pair_korig(q, e);
        uint32_t s2[2];
        split2(w[(size_t)m * KDIM + korig], s2);
        wbits |= s2[t] << (16 * e);
    }
    g_wA[o] = wbits;
}

__global__ void lfbtab_kernel() {
    int i = blockIdx.x * 256 + threadIdx.x;
    if (i < 768) {
        int d = i - 383;
        float v = 0.0f;
        if (d >= -191 && d <= 192)
            v = expf(-(float)(d * d) / (2.0f * 191.0f * 191.0f));
        g_lfbtab[i] = v;
    }
}

// ---------------------------------------------------------------------------
// Conv GEMM (bf16 3-term): CTA 128m x 128n, warp 64m x 32n, KS=32.
// Slot: A 16384B (2 slabs x 2t x 4096) | B 2t x (16 rows x 544B) = 33792B.
// 3 slots = 101376B; epilogue D staging (71680B) fits inside.
// ---------------------------------------------------------------------------
#define SLOT_B    33792
#define SMEM_CONV (3 * SLOT_B)                  // 101376

__global__ __launch_bounds__(256, 2)
void conv_mma_kernel()
{
    extern __shared__ char smem[];
    const uint32_t sb = smem_u32(smem);

    const int tid  = threadIdx.x;
    const int lane = tid & 31;
    const int wid  = tid >> 5;
    const int gid  = lane >> 2;
    const int tig  = lane & 3;
    const int wm   = wid & 1;
    const int wn   = wid >> 1;

    const int mt   = blockIdx.x;
    const int m0   = mt * 128;
    const int bimg = blockIdx.y / 24;
    const int nl0  = (blockIdx.y - bimg * 24) * 128;
    const int imgb = bimg * IMG_SZ;

    float d[4][4][4];
#pragma unroll
    for (int i = 0; i < 4; i++)
#pragma unroll
        for (int j = 0; j < 4; j++)
#pragma unroll
            for (int q = 0; q < 4; q++) d[i][j][q] = 0.0f;

    auto issue_stage = [&](int s, int slot) {
        const uint32_t sa = sb + slot * SLOT_B;
        const uint32_t* asrc = g_wA + (size_t)(mt * NS144 + s * 2) * 2048;
#pragma unroll
        for (int j = 0; j < 4; j++) {           // A: flat 4096-word copy
            int c = j * 256 + tid;
            cp16(sa + c * 16, asrc + c * 4);
        }
#pragma unroll
        for (int j = 0; j < 4; j++) {           // B: 2t x 16 rows x 32 chunks
            int idx = j * 256 + tid;
            int t = idx >> 9, row = (idx >> 5) & 15, cin = idx & 31;
            int q = s * 16 + row;
            int typ, boff;
            if (q < 768) {
                int ci = q / 3, jj = q - ci * 3;
                typ = 0; boff = ci * 3136 + jj * 56;
            } else {
                int p = q - 768; int cp = p / 3, kh = p - cp * 3;
                typ = 1; boff = cp * 6272 + kh * 56;     // aligned (shift in stream)
            }
            const uint32_t* src = g_bp + (size_t)(t * 2 + typ) * XPW
                                + imgb + boff + nl0 + cin * 4;
            cp16(sa + 16384 + t * 8704 + row * 544 + cin * 16, src);
        }
        CP_COMMIT();
    };

    auto compute_stage = [&](int slot) {
        const char* base = smem + slot * SLOT_B;
        const char* Bb = base + 16384;
#pragma unroll
        for (int slab = 0; slab < 2; slab++) {
            uint32_t bfr[2][4][2];
#pragma unroll
            for (int t = 0; t < 2; t++) {
                const char* bt = Bb + t * 8704 + slab * (8 * 544);
#pragma unroll
                for (int nf = 0; nf < 4; nf++) {
                    int nw = (wn * 32 + nf * 8 + gid) * 4;
                    bfr[t][nf][0] = *(const uint32_t*)(bt + tig * 544 + nw);
                    bfr[t][nf][1] = *(const uint32_t*)(bt + (tig + 4) * 544 + nw);
                }
            }
            const char* Ab = base + slab * 8192;
#pragma unroll
            for (int fh = 0; fh < 2; fh++) {
#pragma unroll
                for (int ta = 0; ta < 2; ta++) {
                    uint4 afr[2];
#pragma unroll
                    for (int f2 = 0; f2 < 2; f2++) {
                        int f = wm * 4 + fh * 2 + f2;
                        afr[f2] = *(const uint4*)(Ab + ta * 4096 + f * 512 + lane * 16);
                    }
                    const int ntb = (ta == 0) ? 2 : 1;   // (0,0),(0,1),(1,0)
#pragma unroll
                    for (int tb = 0; tb < 2; tb++) {
                        if (tb < ntb) {
#pragma unroll
                            for (int f2 = 0; f2 < 2; f2++)
#pragma unroll
                                for (int nf = 0; nf < 4; nf++)
                                    mma_bf16(d[fh * 2 + f2][nf], afr[f2],
                                             bfr[tb][nf][0], bfr[tb][nf][1]);
                        }
                    }
                }
            }
        }
    };

    issue_stage(0, 0);
    issue_stage(1, 1);
    for (int s = 0; s < NSTG; s++) {
        CP_WAIT1();
        __syncthreads();
        if (s + 2 < NSTG) issue_stage(s + 2, (s + 2) % 3);
        else CP_COMMIT();
        compute_stage(s % 3);
    }

    // ---- epilogue: D -> smem [n][140] -> coalesced g_y[n][m] ----
    __syncthreads();
    float* ds = (float*)smem;
#pragma unroll
    for (int fm = 0; fm < 4; fm++) {
#pragma unroll
        for (int nf = 0; nf < 4; nf++) {
            int mb = wm * 64 + fm * 16 + gid;
            int nb = wn * 32 + nf * 8 + 2 * tig;
            ds[nb * 140 + mb]           = d[fm][nf][0];
            ds[(nb + 1) * 140 + mb]     = d[fm][nf][1];
            ds[nb * 140 + mb + 8]       = d[fm][nf][2];
            ds[(nb + 1) * 140 + mb + 8] = d[fm][nf][3];
        }
    }
    __syncthreads();
    const int n0g = bimg * IMG_N + nl0;
#pragma unroll
    for (int q = 0; q < 16; q++) {
        int idx = q * 256 + tid;
        int n  = idx >> 5;
        int m4 = idx & 31;
        float4 v = *(const float4*)(ds + n * 140 + m4 * 4);
        *(float4*)(g_y + (size_t)(n0g + n) * COUT_ + m0 + m4 * 4) = v;
    }
}

// ---------------------------------------------------------------------------
// Exact fp32 re-evaluation (sequential k = ci,kh,kw; fmaf chain)
// ---------------------------------------------------------------------------
__device__ float refine_dot(const float* __restrict__ x, const float* __restrict__ w,
                            int b, int h, int wp, int c) {
    const float* wr = w + (size_t)c * KDIM;
    const float* xb = x + ((size_t)b * CIN_) * (HIN_ * HIN_) + h * HIN_ + wp;
    float acc = 0.0f;
    for (int ci = 0; ci < CIN_; ci++) {
        const float* xr = xb + ci * (HIN_ * HIN_);
        const float* wc = wr + ci * 9;
#pragma unroll
        for (int kh = 0; kh < 3; kh++)
#pragma unroll
            for (int kw = 0; kw < 3; kw++)
                acc = fmaf(xr[kh * HIN_ + kw], wc[kh * 3 + kw], acc);
    }
    return acc;
}

// ---------------------------------------------------------------------------
// WTA + Gaussian LFB gating (27 pixels/block) with near-tie refinement
// ---------------------------------------------------------------------------
#define SYP 388

__global__ __launch_bounds__(256)
void wta_lfb_kernel(const float* __restrict__ xg, const float* __restrict__ wg,
                    float* __restrict__ out) {
    __shared__ float sy[27 * SYP];
    __shared__ float stab[768];
    __shared__ int   wcnt[27];
    __shared__ int   wlist[27][4];
    __shared__ int   ccnt[27];
    __shared__ int   cand[27][8];

    const int tid = threadIdx.x;
    const int b   = blockIdx.z;
    const int h   = blockIdx.y;
    const int w0  = blockIdx.x * 27;

    const size_t base = ((size_t)b * IMG_N + h * HIN_ + w0) * COUT_;

    for (int i4 = tid; i4 < 27 * 96; i4 += 256) {
        float4 v = *(const float4*)(g_y + base + (size_t)i4 * 4);
        int j  = i4 / 96;
        int c4 = i4 - j * 96;
        *(float4*)&sy[j * SYP + c4 * 4] = v;
    }
    if (tid < 192) {
        float4 t = *(const float4*)(g_lfbtab + tid * 4);
        *(float4*)&stab[tid * 4] = t;
    }
    if (tid < 27) { wcnt[tid] = 0; ccnt[tid] = 0; }
    __syncthreads();

    const int wd   = tid >> 5;
    const int lane = tid & 31;
    for (int j = wd; j < 27; j += 8) {
        const float* p = &sy[j * SYP];
        float mx = -FLT_MAX;
#pragma unroll
        for (int q = 0; q < 12; q++) mx = fmaxf(mx, p[lane + q * 32]);
#pragma unroll
        for (int o = 16; o; o >>= 1) mx = fmaxf(mx, __shfl_xor_sync(0xffffffffu, mx, o));
        const float thr = mx - TAU;
#pragma unroll
        for (int q = 0; q < 12; q++) {
            int c = lane + q * 32;
            if (p[c] >= thr) {
                int pos = atomicAdd(&ccnt[j], 1);
                if (pos < 8) cand[j][pos] = c;
            }
        }
        __syncwarp();
        int nc = ccnt[j]; if (nc > 8) nc = 8;
        if (nc == 1) {
            if (lane == 0) { wlist[j][0] = cand[j][0]; wcnt[j] = 1; }
        } else {
            float rv = -FLT_MAX;
            if (lane < nc) rv = refine_dot(xg, wg, b, h, w0 + j, cand[j][lane]);
            float rmx = rv;
#pragma unroll
            for (int o = 16; o; o >>= 1) rmx = fmaxf(rmx, __shfl_xor_sync(0xffffffffu, rmx, o));
            if (lane < nc && rv == rmx) {
                int pos = atomicAdd(&wcnt[j], 1);
                if (pos < 4) wlist[j][pos] = cand[j][lane];
            }
        }
    }
    __syncthreads();

    int c = tid / 27;
    int j = tid - c * 27;
    const size_t obase = (((size_t)b * COUT_) * HO_ + h) * HO_ + w0;
    while (c < COUT_) {
        float yv = sy[j * SYP + c];
        int nw = wcnt[j];
        float lfb = stab[wlist[j][0] - c + 383];
        if (nw > 1) {
            if (nw > 4) nw = 4;
            for (int t = 1; t < nw; t++)
                lfb += stab[wlist[j][t] - c + 383];
            lfb = fminf(lfb, 1.0f);
        }
        out[obase + (size_t)c * (HO_ * HO_) + j] = lfb * yv;
        c += 9; j += 13;
        if (j >= 27) { j -= 27; c += 1; }
    }
}

// ---------------------------------------------------------------------------
extern "C" void kernel_launch(void* const* d_in, const int* in_sizes, int n_in,
                              void* d_out, int out_size) {
    const float* x = (const float*)d_in[0];   // (16,256,56,56)
    const float* w = (const float*)d_in[1];   // (384,256,3,3)
    float* out = (float*)d_out;               // (16,384,54,54)

    cudaFuncSetAttribute(conv_mma_kernel,
                         cudaFuncAttributeMaxDynamicSharedMemorySize, SMEM_CONV);

    split_pack_kernel<<<(unsigned)((XELEMS / 4 + 255) / 256), 256>>>(x);
    wprep_kernel<<<(AWORDS + 255) / 256, 256>>>(w);
    lfbtab_kernel<<<3, 256>>>();              // conv at launch idx 3 (ncu -s 5)

    dim3 g1(3, B_SZ * 24);                    // m fastest -> B reuse in L2
    conv_mma_kernel<<<g1, 256, SMEM_CONV>>>();

    dim3 g2(2, HO_, B_SZ);
    wta_lfb_kernel<<<g2, 256>>>(x, w, out);
}